// round 1
// baseline (speedup 1.0000x reference)
#include <cuda_runtime.h>
#include <math.h>

#define N_NODES 8192
#define MAXD 128

// ---------------- scratch (device globals; no allocation allowed) ----------
__device__ __align__(16) float d_h1 [N_NODES * 64];
__device__ __align__(16) float d_h  [N_NODES * 128];
__device__ __align__(16) float d_msg[N_NODES * 128];
__device__ __align__(16) float d_g  [N_NODES * 128];
__device__ __align__(16) float d_f  [N_NODES * 256];   // [g | h]
__device__ __align__(16) float d_p1 [N_NODES * 128];
__device__ __align__(16) float d_p2 [N_NODES * 64];
__device__ float d_dinv[N_NODES];
__device__ int   d_cnt [N_NODES];
__device__ int   d_nbr [N_NODES * MAXD];

// ---------------- generic register-tiled GEMM: out = act(in @ W^T + b) -----
// in: [N, K] (row stride in_stride), W: [M, K] row-major, out row stride out_stride.
// Optional dual write (out2) used to build the concat buffer without a copy.
constexpr int BR = 32;   // rows per block
constexpr int KC = 32;   // k-chunk

template <int K, int M, bool RELU>
__global__ void __launch_bounds__(256)
gemm_rt(const float* __restrict__ in, int in_stride,
        const float* __restrict__ W, const float* __restrict__ bias,
        float* __restrict__ out, int out_stride,
        float* __restrict__ out2, int out2_stride)
{
    constexpr int TX  = M / 4;        // threads across M (each owns 4 cols)
    constexpr int TY  = 256 / TX;
    constexpr int RPT = BR / TY;      // rows per thread

    __shared__ float4 in_sh[BR][KC / 4];     // 4 KB
    __shared__ float4 wt_sh[KC][M / 4];      // <= 16 KB, W transposed
    float* wt_s = (float*)wt_sh;

    const int tid  = threadIdx.x;
    const int tx   = tid % TX;
    const int ty   = tid / TX;
    const int row0 = blockIdx.x * BR;

    float4 acc[RPT];
#pragma unroll
    for (int r = 0; r < RPT; r++) acc[r] = make_float4(0.f, 0.f, 0.f, 0.f);

    for (int k0 = 0; k0 < K; k0 += KC) {
        // ---- load input tile (coalesced float4) ----
        {
            int r = tid >> 3;          // KC/4 == 8
            int v = tid & 7;
            in_sh[r][v] = *(const float4*)(in + (size_t)(row0 + r) * in_stride + k0 + v * 4);
        }
        // ---- load weight tile, store transposed ----
        {
            int v = tid & 7;
#pragma unroll
            for (int m = tid >> 3; m < M; m += 32) {
                float4 w = *(const float4*)(W + (size_t)m * K + k0 + v * 4);
                wt_s[(v * 4 + 0) * M + m] = w.x;
                wt_s[(v * 4 + 1) * M + m] = w.y;
                wt_s[(v * 4 + 2) * M + m] = w.z;
                wt_s[(v * 4 + 3) * M + m] = w.w;
            }
        }
        __syncthreads();

#pragma unroll
        for (int kv = 0; kv < KC / 4; kv++) {
            float4 w0 = wt_sh[kv * 4 + 0][tx];
            float4 w1 = wt_sh[kv * 4 + 1][tx];
            float4 w2 = wt_sh[kv * 4 + 2][tx];
            float4 w3 = wt_sh[kv * 4 + 3][tx];
#pragma unroll
            for (int rr = 0; rr < RPT; rr++) {
                float4 a = in_sh[ty * RPT + rr][kv];
                acc[rr].x += a.x * w0.x + a.y * w1.x + a.z * w2.x + a.w * w3.x;
                acc[rr].y += a.x * w0.y + a.y * w1.y + a.z * w2.y + a.w * w3.y;
                acc[rr].z += a.x * w0.z + a.y * w1.z + a.z * w2.z + a.w * w3.z;
                acc[rr].w += a.x * w0.w + a.y * w1.w + a.z * w2.w + a.w * w3.w;
            }
        }
        __syncthreads();
    }

    float4 bb = make_float4(0.f, 0.f, 0.f, 0.f);
    if (bias) bb = *(const float4*)(bias + tx * 4);

#pragma unroll
    for (int rr = 0; rr < RPT; rr++) {
        int r = row0 + ty * RPT + rr;
        float4 o;
        o.x = acc[rr].x + bb.x;
        o.y = acc[rr].y + bb.y;
        o.z = acc[rr].z + bb.z;
        o.w = acc[rr].w + bb.w;
        if (RELU) {
            o.x = fmaxf(o.x, 0.f); o.y = fmaxf(o.y, 0.f);
            o.z = fmaxf(o.z, 0.f); o.w = fmaxf(o.w, 0.f);
        }
        *(float4*)(out + (size_t)r * out_stride + tx * 4) = o;
        if (out2)
            *(float4*)(out2 + (size_t)r * out2_stride + tx * 4) = o;
    }
}

// ---------------- pass 1 over adj: degree + capped CSR ---------------------
__global__ void __launch_bounds__(256)
degcsr_kernel(const float* __restrict__ adj)
{
    const int row = blockIdx.x;
    __shared__ int s_cnt;
    if (threadIdx.x == 0) s_cnt = 0;
    __syncthreads();

    const float4* a4 = (const float4*)(adj + (size_t)row * N_NODES);
    const int n4 = N_NODES / 4;
    int* nbr = d_nbr + (size_t)row * MAXD;

    for (int i = threadIdx.x; i < n4; i += 256) {
        float4 v = a4[i];
        if (v.x != 0.f) { int p = atomicAdd(&s_cnt, 1); if (p < MAXD) nbr[p] = i * 4 + 0; }
        if (v.y != 0.f) { int p = atomicAdd(&s_cnt, 1); if (p < MAXD) nbr[p] = i * 4 + 1; }
        if (v.z != 0.f) { int p = atomicAdd(&s_cnt, 1); if (p < MAXD) nbr[p] = i * 4 + 2; }
        if (v.w != 0.f) { int p = atomicAdd(&s_cnt, 1); if (p < MAXD) nbr[p] = i * 4 + 3; }
    }
    __syncthreads();
    if (threadIdx.x == 0) {
        int cn = s_cnt;
        d_cnt[row]  = cn < MAXD ? cn : MAXD;
        d_dinv[row] = rsqrtf((float)cn + 1.0f);   // self loop adds 1
    }
}

// ---------------- sparse aggregation + relu(agg + bg) ----------------------
// g[i,c] = relu( dinv_i * ( dinv_i*msg[i,c] + sum_j dinv_j*msg[j,c] ) + bg[c] )
__global__ void __launch_bounds__(128)
agg_kernel(const float* __restrict__ msg, const float* __restrict__ bg,
           float* __restrict__ g)
{
    const int row = blockIdx.x;
    const int c   = threadIdx.x;           // 128 threads = feature dim

    __shared__ int   s_idx[MAXD];
    __shared__ float s_dj [MAXD];

    const int   cnt = d_cnt[row];
    const float di  = d_dinv[row];

    if (c < cnt) {
        int j = d_nbr[(size_t)row * MAXD + c];
        s_idx[c] = j;
        s_dj[c]  = d_dinv[j];
    }
    __syncthreads();

    float acc0 = di * msg[(size_t)row * 128 + c];   // self-loop term
    float acc1 = 0.f;
    int k = 0;
    for (; k + 1 < cnt; k += 2) {
        acc0 += s_dj[k]     * msg[(size_t)s_idx[k]     * 128 + c];
        acc1 += s_dj[k + 1] * msg[(size_t)s_idx[k + 1] * 128 + c];
    }
    if (k < cnt) acc0 += s_dj[k] * msg[(size_t)s_idx[k] * 128 + c];

    float v = di * (acc0 + acc1) + bg[c];
    g[(size_t)row * 128 + c] = fmaxf(v, 0.f);
}

// ---------------- final small GEMM (M=8) + mask -----------------------------
__global__ void __launch_bounds__(256)
out_kernel(const float* __restrict__ q,   // [N,64]
           const float* __restrict__ wo,  // [8,64]
           const float* __restrict__ bo,  // [8]
           const float* __restrict__ mask,
           float* __restrict__ out)       // [N,8]
{
    __shared__ float q_sh[32][65];
    __shared__ float wo_sh[8][65];
    __shared__ float bo_sh[8];

    const int tid  = threadIdx.x;
    const int row0 = blockIdx.x * 32;

    for (int i = tid; i < 32 * 64; i += 256) {
        int r = i / 64, k = i % 64;
        q_sh[r][k] = q[(size_t)(row0 + r) * 64 + k];
    }
    for (int i = tid; i < 8 * 64; i += 256)
        wo_sh[i / 64][i % 64] = wo[i];
    if (tid < 8) bo_sh[tid] = bo[tid];
    __syncthreads();

    const int r = tid / 8, m = tid % 8;
    float acc = 0.f;
#pragma unroll
    for (int k = 0; k < 64; k++) acc += q_sh[r][k] * wo_sh[m][k];

    out[(size_t)(row0 + r) * 8 + m] = (acc + bo_sh[m]) * mask[row0 + r];
}

// ---------------- launch ----------------------------------------------------
extern "C" void kernel_launch(void* const* d_in, const int* in_sizes, int n_in,
                              void* d_out, int out_size)
{
    const float* x    = (const float*)d_in[0];
    const float* adj  = (const float*)d_in[1];
    const float* mask = (const float*)d_in[2];
    const float* w1   = (const float*)d_in[3];
    const float* b1   = (const float*)d_in[4];
    const float* w2   = (const float*)d_in[5];
    const float* b2   = (const float*)d_in[6];
    const float* wg   = (const float*)d_in[7];
    const float* bg   = (const float*)d_in[8];
    const float* wd   = (const float*)d_in[9];
    const float* bd   = (const float*)d_in[10];
    const float* wp1  = (const float*)d_in[11];
    const float* bp1  = (const float*)d_in[12];
    const float* wp2  = (const float*)d_in[13];
    const float* bp2  = (const float*)d_in[14];
    const float* wo   = (const float*)d_in[15];
    const float* bo   = (const float*)d_in[16];
    float* out = (float*)d_out;

    float *p_h1, *p_h, *p_msg, *p_g, *p_f, *p_p1, *p_p2;
    cudaGetSymbolAddress((void**)&p_h1,  d_h1);
    cudaGetSymbolAddress((void**)&p_h,   d_h);
    cudaGetSymbolAddress((void**)&p_msg, d_msg);
    cudaGetSymbolAddress((void**)&p_g,   d_g);
    cudaGetSymbolAddress((void**)&p_f,   d_f);
    cudaGetSymbolAddress((void**)&p_p1,  d_p1);
    cudaGetSymbolAddress((void**)&p_p2,  d_p2);

    const int GB = N_NODES / BR;   // 256 blocks

    // encoder
    gemm_rt<32, 64, true ><<<GB, 256>>>(x,    32, w1, b1, p_h1, 64,  nullptr, 0);
    gemm_rt<64, 128, true><<<GB, 256>>>(p_h1, 64, w2, b2, p_h,  128, p_f + 128, 256); // h also -> f[:,128:]
    // message
    gemm_rt<128, 128, false><<<GB, 256>>>(p_h, 128, wg, nullptr, p_msg, 128, nullptr, 0);
    // graph structure (single dense pass over adj)
    degcsr_kernel<<<N_NODES, 256>>>(adj);
    // normalized aggregation + relu(+bg)
    agg_kernel<<<N_NODES, 128>>>(p_msg, bg, p_g);
    // decoder
    gemm_rt<128, 128, true><<<GB, 256>>>(p_g,  128, wd,  bd,  p_f,  256, nullptr, 0); // -> f[:,0:128]
    gemm_rt<256, 128, true><<<GB, 256>>>(p_f,  256, wp1, bp1, p_p1, 128, nullptr, 0);
    gemm_rt<128, 64,  true><<<GB, 256>>>(p_p1, 128, wp2, bp2, p_p2, 64,  nullptr, 0);
    // output + mask
    out_kernel<<<N_NODES / 32, 256>>>(p_p2, wo, bo, mask, out);
}